// round 6
// baseline (speedup 1.0000x reference)
#include <cuda_runtime.h>
#include <math.h>

// Shapes fixed by the dataset: x[4,8192,1024] f32, W[64,1024] f32.
constexpr int H   = 1024;   // hidden
constexpr int EB  = 64;     // experts
constexpr int TB  = 64;     // tokens per block
constexpr int KC  = 32;     // K chunk
constexpr int NCH = H / KC; // 32 chunks
constexpr int NT  = 256;    // threads per block

// Shared memory overlay:
//   phase 1 (GEMM pipeline): xs[2][KC][TB+1] (16640 B) + ws[2][KC][EB+1] (16640 B)
//   phase 2 (epilogue):      logits[TB][EB+1] (16640 B)
// Total static: 33280 B.
constexpr int XS_ELEMS = 2 * KC * (TB + 1);
constexpr int WS_ELEMS = 2 * KC * (EB + 1);
constexpr int SMEM_FLOATS = XS_ELEMS + WS_ELEMS;

__global__ void zero_out_kernel(float* __restrict__ out, int n)
{
    int i = blockIdx.x * blockDim.x + threadIdx.x;
    if (i < n) out[i] = 0.0f;
}

__global__ __launch_bounds__(NT, 4)
void moe_gate_kernel(const float* __restrict__ x,
                     const float* __restrict__ W,
                     float* __restrict__ out,
                     int T, int out_size)
{
    __shared__ float smem[SMEM_FLOATS];

    // Phase-1 views
    float (*xs)[KC][TB + 1] = reinterpret_cast<float (*)[KC][TB + 1]>(smem);
    float (*ws)[KC][EB + 1] = reinterpret_cast<float (*)[KC][EB + 1]>(smem + XS_ELEMS);
    // Phase-2 view (reused after a full sync)
    float (*logits)[EB + 1] = reinterpret_cast<float (*)[EB + 1]>(smem);

    const int tid = threadIdx.x;
    const int t0  = blockIdx.x * TB;

    // Compute fragment mapping: 16x16 thread grid.
    // tokens: contiguous 4 (tokid*4+i); experts: strided (expid + 16*j)
    const int tokid = tid >> 4;   // 0..15
    const int expid = tid & 15;   // 0..15

    // Loader mapping: f0 = float4 column within chunk, r0 = row.
    const int f0 = tid & 7;       // 0..7  (k offset = f0*4)
    const int r0 = tid >> 3;      // 0..31 (second row: r0+32)

    float acc[4][4];
    #pragma unroll
    for (int i = 0; i < 4; i++)
        #pragma unroll
        for (int j = 0; j < 4; j++)
            acc[i][j] = 0.0f;

    float4 px0, px1, pw0, pw1;

    // ---- prologue load: chunk 0 ----
    {
        const int kb = f0 * 4;
        const int ta = t0 + r0, tb2 = t0 + r0 + 32;
        px0 = (ta  < T) ? *reinterpret_cast<const float4*>(x + (size_t)ta  * H + kb)
                        : make_float4(0.f, 0.f, 0.f, 0.f);
        px1 = (tb2 < T) ? *reinterpret_cast<const float4*>(x + (size_t)tb2 * H + kb)
                        : make_float4(0.f, 0.f, 0.f, 0.f);
        pw0 = *reinterpret_cast<const float4*>(W + (size_t)r0        * H + kb);
        pw1 = *reinterpret_cast<const float4*>(W + (size_t)(r0 + 32) * H + kb);
    }

    for (int c = 0; c < NCH; ++c) {
        const int buf = c & 1;
        // ---- stage current chunk into smem (transposed, conflict-free) ----
        {
            const int k4 = f0 * 4;
            xs[buf][k4 + 0][r0]      = px0.x;
            xs[buf][k4 + 1][r0]      = px0.y;
            xs[buf][k4 + 2][r0]      = px0.z;
            xs[buf][k4 + 3][r0]      = px0.w;
            xs[buf][k4 + 0][r0 + 32] = px1.x;
            xs[buf][k4 + 1][r0 + 32] = px1.y;
            xs[buf][k4 + 2][r0 + 32] = px1.z;
            xs[buf][k4 + 3][r0 + 32] = px1.w;

            ws[buf][k4 + 0][r0]      = pw0.x;
            ws[buf][k4 + 1][r0]      = pw0.y;
            ws[buf][k4 + 2][r0]      = pw0.z;
            ws[buf][k4 + 3][r0]      = pw0.w;
            ws[buf][k4 + 0][r0 + 32] = pw1.x;
            ws[buf][k4 + 1][r0 + 32] = pw1.y;
            ws[buf][k4 + 2][r0 + 32] = pw1.z;
            ws[buf][k4 + 3][r0 + 32] = pw1.w;
        }
        __syncthreads();

        // ---- prefetch next chunk from gmem (overlaps with FFMA below) ----
        if (c + 1 < NCH) {
            const int kb = (c + 1) * KC + f0 * 4;
            const int ta = t0 + r0, tb2 = t0 + r0 + 32;
            px0 = (ta  < T) ? *reinterpret_cast<const float4*>(x + (size_t)ta  * H + kb)
                            : make_float4(0.f, 0.f, 0.f, 0.f);
            px1 = (tb2 < T) ? *reinterpret_cast<const float4*>(x + (size_t)tb2 * H + kb)
                            : make_float4(0.f, 0.f, 0.f, 0.f);
            pw0 = *reinterpret_cast<const float4*>(W + (size_t)r0        * H + kb);
            pw1 = *reinterpret_cast<const float4*>(W + (size_t)(r0 + 32) * H + kb);
        }

        // ---- compute on staged chunk ----
        #pragma unroll 8
        for (int kk = 0; kk < KC; ++kk) {
            float a[4], b[4];
            #pragma unroll
            for (int i = 0; i < 4; i++) a[i] = xs[buf][kk][tokid * 4 + i];
            #pragma unroll
            for (int j = 0; j < 4; j++) b[j] = ws[buf][kk][expid + 16 * j];
            #pragma unroll
            for (int i = 0; i < 4; i++)
                #pragma unroll
                for (int j = 0; j < 4; j++)
                    acc[i][j] = fmaf(a[i], b[j], acc[i][j]);
        }
        // Next iteration stages into buf^1 (not read by this compute); the
        // __syncthreads at the top of the next iteration orders stage->compute.
    }

    // Drain all pipeline-buffer readers before overlaying logits.
    __syncthreads();

    #pragma unroll
    for (int i = 0; i < 4; i++)
        #pragma unroll
        for (int j = 0; j < 4; j++)
            logits[tokid * 4 + i][expid + 16 * j] = acc[i][j];
    __syncthreads();

    // ---- epilogue: one thread per token ----
    if (tid < TB) {
        const int gt = t0 + tid;
        if (gt < T) {
            const float* row = logits[tid];
            float l1 = -INFINITY, l2 = -INFINITY;
            int   i1 = 0, i2 = 0;
            #pragma unroll 8
            for (int e = 0; e < EB; ++e) {
                float v = row[e];
                if (v > l1)      { l2 = l1; i2 = i1; l1 = v; i1 = e; }
                else if (v > l2) { l2 = v;  i2 = e; }
            }
            float denom = 0.0f;
            #pragma unroll 8
            for (int e = 0; e < EB; ++e) denom += expf(row[e] - l1);

            const float p1 = 1.0f / denom;            // softmax prob of top-1
            const float p2 = expf(l2 - l1) / denom;   // softmax prob of top-2
            // renormalize: softmax([p1, p2]) in fp32, p1 >= p2
            const float d  = expf(p2 - p1);
            const float s1 = 1.0f / (1.0f + d);
            const float s2 = d / (1.0f + d);

            // Packing: [top_scores (2T)] [top_idx as float (2T)] [rest = 0]
            const long long o1 = 2LL * gt;
            if (o1 + 1 < out_size) { out[o1] = s1; out[o1 + 1] = s2; }
            const long long o2 = 2LL * T + 2LL * gt;
            if (o2 + 1 < out_size) { out[o2] = (float)i1; out[o2 + 1] = (float)i2; }
        }
    }
}

extern "C" void kernel_launch(void* const* d_in, const int* in_sizes, int n_in,
                              void* d_out, int out_size)
{
    const float* x = (const float*)d_in[0];
    const float* W = (const float*)d_in[1];
    float* out = (float*)d_out;

    const int T = in_sizes[0] / H;          // 32768
    const int grid = (T + TB - 1) / TB;     // 512

    // Zero the whole output first (harness poisons it to 0xAA; the reference's
    // third output is a zero scalar, and this makes us robust to packing gaps).
    if (out_size > 0) {
        const int zt = 256;
        zero_out_kernel<<<(out_size + zt - 1) / zt, zt>>>(out, out_size);
    }

    moe_gate_kernel<<<grid, NT>>>(x, W, out, T, out_size);
}